// round 6
// baseline (speedup 1.0000x reference)
#include <cuda_runtime.h>
#include <cuda_fp16.h>
#include <cstdint>

#define IN_DIM 128
#define OUT_DIM 64
#define MAXN 50000
#define MAXE 1600000
#define SLOPE 0.1f
#define EPS 1e-12f
#define SCAN_BLK 1024
#define MAX_SCAN_BLOCKS 64

// Scratch (static device globals — allocation is forbidden). Zero-init at load.
__device__ __align__(256) __half g_newh[MAXN * OUT_DIM]; // transformed features, fp16
__device__ float  g_ssrc[MAXN];          // new[n] . a_src
__device__ float  g_sdst[MAXN];          // new[n] . a_dst
__device__ int    g_cnt[MAXN];           // out-degree histogram (zeroed by k_aggregate)
__device__ int    g_base[MAXN];          // CSR offsets (mutated by k_place into end[])
__device__ __align__(16) float2 g_edge[MAXE];  // src-sorted {ev, dst_bits}
__device__ int    g_bsum[MAX_SCAN_BLOCKS];   // scan block aggregates
__device__ int    g_flag[MAX_SCAN_BLOCKS];   // scan publish flags (zeroed by k_fused)

// ---------------------------------------------------------------------------
// Kernel 1 (fused): blocks [0, nbT): transform new = x@W^T+b via packed
//   fma.rn.f32x2 (2 MACs/inst, full fp32), W transposed in smem so one
//   LDS.128 (v2.u64) feeds two FFMA2. Blocks [nbT,...): histogram of src.
// ---------------------------------------------------------------------------
__global__ __launch_bounds__(256) void k_fused(
    const float* __restrict__ x, const float* __restrict__ W,
    const float* __restrict__ b, const float* __restrict__ a,
    const int* __restrict__ eidx, int nN, int nE, int nbT)
{
    if ((int)blockIdx.x >= nbT) {
        // ---- histogram part ----
        int tidg   = (blockIdx.x - nbT) * blockDim.x + threadIdx.x;
        int stride = (gridDim.x - nbT) * blockDim.x;
        for (int e = tidg; e < nE; e += stride) {
            int s = eidx[e];
            s = min(max(s, 0), nN - 1);
            atomicAdd(&g_cnt[s], 1);
        }
        return;
    }

    // ---- transform part ----
    if (blockIdx.x == 0 && threadIdx.x < MAX_SCAN_BLOCKS) g_flag[threadIdx.x] = 0;

    // W transposed: sWT[k*64 + d] = W[d*128 + k]; rows are 256B-aligned.
    __shared__ __align__(16) float sWT[IN_DIM * OUT_DIM];
    __shared__ float sb[OUT_DIM], sas[OUT_DIM], sad[OUT_DIM];
    for (int i = threadIdx.x; i < OUT_DIM * IN_DIM; i += blockDim.x) {
        int d = i >> 7;          // 0..63
        int k = i & 127;         // 0..127
        sWT[k * OUT_DIM + d] = W[i];
    }
    if (threadIdx.x < OUT_DIM) {
        sb[threadIdx.x]  = b[threadIdx.x];
        sas[threadIdx.x] = a[threadIdx.x];
        sad[threadIdx.x] = a[OUT_DIM + threadIdx.x];
    }
    __syncthreads();

    int n = blockIdx.x * blockDim.x + threadIdx.x;
    if (n >= nN) return;

    const float4* __restrict__ x4 = (const float4*)(x + (size_t)n * IN_DIM);

    unsigned long long acc2[OUT_DIM / 2];   // packed f32x2: acc2[p] = {d=2p, d=2p+1}
#pragma unroll
    for (int p = 0; p < OUT_DIM / 2; p++) acc2[p] = 0ULL;

    for (int kk = 0; kk < IN_DIM / 4; kk++) {
        float4 xv = x4[kk];
        float xs0 = xv.x, xs1 = xv.y, xs2 = xv.z, xs3 = xv.w;
#pragma unroll
        for (int t = 0; t < 4; t++) {
            float xst = (t == 0) ? xs0 : (t == 1) ? xs1 : (t == 2) ? xs2 : xs3;
            unsigned long long xp;
            asm("mov.b64 %0, {%1, %1};" : "=l"(xp) : "f"(xst));
            const ulonglong2* wrow =
                (const ulonglong2*)(sWT + (kk * 4 + t) * OUT_DIM);
#pragma unroll
            for (int j = 0; j < OUT_DIM / 4; j++) {
                ulonglong2 w2 = wrow[j];   // {d=4j..4j+3} as two packed pairs
                asm("fma.rn.f32x2 %0, %1, %2, %0;"
                    : "+l"(acc2[2 * j])     : "l"(w2.x), "l"(xp));
                asm("fma.rn.f32x2 %0, %1, %2, %0;"
                    : "+l"(acc2[2 * j + 1]) : "l"(w2.y), "l"(xp));
            }
        }
    }

    // unpack, add bias, scores, fp16 store
    float v[OUT_DIM];
#pragma unroll
    for (int p = 0; p < OUT_DIM / 2; p++) {
        float lo, hi;
        asm("mov.b64 {%0, %1}, %2;" : "=f"(lo), "=f"(hi) : "l"(acc2[p]));
        v[2 * p]     = lo + sb[2 * p];
        v[2 * p + 1] = hi + sb[2 * p + 1];
    }

    float ss = 0.f, sd = 0.f;
    uint2* newh = (uint2*)(g_newh + ((size_t)n << 6));
#pragma unroll
    for (int j = 0; j < OUT_DIM / 4; j++) {
        __half2 h0 = __float22half2_rn(make_float2(v[4*j+0], v[4*j+1]));
        __half2 h1 = __float22half2_rn(make_float2(v[4*j+2], v[4*j+3]));
        uint2 hv;
        hv.x = *(unsigned int*)&h0;
        hv.y = *(unsigned int*)&h1;
        newh[j] = hv;
        ss += v[4*j+0]*sas[4*j+0] + v[4*j+1]*sas[4*j+1]
            + v[4*j+2]*sas[4*j+2] + v[4*j+3]*sas[4*j+3];
        sd += v[4*j+0]*sad[4*j+0] + v[4*j+1]*sad[4*j+1]
            + v[4*j+2]*sad[4*j+2] + v[4*j+3]*sad[4*j+3];
    }
    g_ssrc[n] = ss;
    g_sdst[n] = sd;
}

// ---------------------------------------------------------------------------
// Kernel 2: exclusive scan of g_cnt -> g_base, decoupled lookback.
// 49 blocks, all concurrently resident so the spin cannot deadlock.
// ---------------------------------------------------------------------------
__global__ __launch_bounds__(SCAN_BLK) void k_scan(int nN)
{
    __shared__ int swarp[32];
    __shared__ int s_total;
    __shared__ int s_boff;
    int tid  = threadIdx.x;
    int lane = tid & 31;
    int wid  = tid >> 5;
    int bid  = blockIdx.x;
    int i    = bid * SCAN_BLK + tid;

    int v = (i < nN) ? g_cnt[i] : 0;

    int inc = v;
#pragma unroll
    for (int off = 1; off < 32; off <<= 1) {
        int t = __shfl_up_sync(0xFFFFFFFF, inc, off);
        if (lane >= off) inc += t;
    }
    if (lane == 31) swarp[wid] = inc;
    __syncthreads();
    if (wid == 0) {
        int wv = swarp[lane];
        int winc = wv;
#pragma unroll
        for (int off = 1; off < 32; off <<= 1) {
            int t = __shfl_up_sync(0xFFFFFFFF, winc, off);
            if (lane >= off) winc += t;
        }
        swarp[lane] = winc - wv;
    }
    __syncthreads();
    int incl = swarp[wid] + inc;
    if (tid == SCAN_BLK - 1) s_total = incl;
    __syncthreads();

    if (tid == 0) {
        g_bsum[bid] = s_total;
        __threadfence();
        *(volatile int*)&g_flag[bid] = 1;
    }

    if (wid == 0) {
        int off = 0;
        for (int base = 0; base < bid; base += 32) {
            int j = base + lane;
            int vj = 0;
            if (j < bid) {
                while (*(volatile int*)&g_flag[j] == 0) {}
                __threadfence();
                vj = *(volatile int*)&g_bsum[j];
            }
#pragma unroll
            for (int o = 16; o > 0; o >>= 1)
                vj += __shfl_down_sync(0xFFFFFFFF, vj, o);
            off += __shfl_sync(0xFFFFFFFF, vj, 0);
        }
        if (lane == 0) s_boff = off;
    }
    __syncthreads();

    if (i < nN) g_base[i] = s_boff + incl - v;
}

// ---------------------------------------------------------------------------
// Kernel 3: per-edge score -> ev once; place {ev,dst} into CSR slot.
// ---------------------------------------------------------------------------
__global__ __launch_bounds__(256) void k_place(
    const int* __restrict__ eidx, int nE, int nN)
{
    int e = blockIdx.x * blockDim.x + threadIdx.x;
    if (e >= nE) return;
    int s = eidx[e];
    int d = eidx[(size_t)nE + e];
    s = min(max(s, 0), nN - 1);
    d = min(max(d, 0), nN - 1);
    float sc = g_ssrc[s] + g_sdst[d];
    sc = sc > 0.f ? sc : SLOPE * sc;
    float ev = __expf(sc);
    int pos = atomicAdd(&g_base[s], 1);
    g_edge[pos] = make_float2(ev, __int_as_float(d));
}

// ---------------------------------------------------------------------------
// Kernel 4: gather-aggregate + normalize. 16 lanes/node; unrolled x4 so each
// thread keeps 4 independent 128B line-gathers in flight (latency-bound fix).
// ---------------------------------------------------------------------------
__global__ __launch_bounds__(256) void k_aggregate(
    float* __restrict__ out, int nN)
{
    int n = blockIdx.x * 16 + (threadIdx.x >> 4);
    int c = threadIdx.x & 15;
    if (n >= nN) return;

    int beg = (n == 0) ? 0 : g_base[n - 1];
    int end = g_base[n];

    float4 acc = make_float4(0.f, 0.f, 0.f, 0.f);
    float rs = 0.f;
    int i = beg;
    for (; i + 4 <= end; i += 4) {
        float2 p0 = g_edge[i];
        float2 p1 = g_edge[i + 1];
        float2 p2 = g_edge[i + 2];
        float2 p3 = g_edge[i + 3];
        uint2 hv0 = *(const uint2*)(g_newh + ((size_t)__float_as_int(p0.y) << 6) + c * 4);
        uint2 hv1 = *(const uint2*)(g_newh + ((size_t)__float_as_int(p1.y) << 6) + c * 4);
        uint2 hv2 = *(const uint2*)(g_newh + ((size_t)__float_as_int(p2.y) << 6) + c * 4);
        uint2 hv3 = *(const uint2*)(g_newh + ((size_t)__float_as_int(p3.y) << 6) + c * 4);
        float2 a0 = __half22float2(*(__half2*)&hv0.x), b0 = __half22float2(*(__half2*)&hv0.y);
        float2 a1 = __half22float2(*(__half2*)&hv1.x), b1 = __half22float2(*(__half2*)&hv1.y);
        float2 a2 = __half22float2(*(__half2*)&hv2.x), b2 = __half22float2(*(__half2*)&hv2.y);
        float2 a3 = __half22float2(*(__half2*)&hv3.x), b3 = __half22float2(*(__half2*)&hv3.y);
        acc.x += p0.x * a0.x + p1.x * a1.x + p2.x * a2.x + p3.x * a3.x;
        acc.y += p0.x * a0.y + p1.x * a1.y + p2.x * a2.y + p3.x * a3.y;
        acc.z += p0.x * b0.x + p1.x * b1.x + p2.x * b2.x + p3.x * b3.x;
        acc.w += p0.x * b0.y + p1.x * b1.y + p2.x * b2.y + p3.x * b3.y;
        rs += (p0.x + p1.x) + (p2.x + p3.x);
    }
    for (; i < end; i++) {
        float2 p = g_edge[i];
        uint2 hv = *(const uint2*)(g_newh + ((size_t)__float_as_int(p.y) << 6) + c * 4);
        float2 a0 = __half22float2(*(__half2*)&hv.x);
        float2 b0 = __half22float2(*(__half2*)&hv.y);
        acc.x += p.x * a0.x;
        acc.y += p.x * a0.y;
        acc.z += p.x * b0.x;
        acc.w += p.x * b0.y;
        rs += p.x;
    }
    float inv = 1.f / (rs + EPS);
    acc.x *= inv; acc.y *= inv; acc.z *= inv; acc.w *= inv;
    *(float4*)(out + ((size_t)n << 6) + c * 4) = acc;

    if (c == 0) g_cnt[n] = 0;   // clean for next launch (graph replay)
}

// ---------------------------------------------------------------------------
extern "C" void kernel_launch(void* const* d_in, const int* in_sizes, int n_in,
                              void* d_out, int out_size)
{
    const float* x    = (const float*)d_in[0];
    const int*   eidx = (const int*)d_in[1];    // int32 (JAX x64 disabled)
    const float* W    = (const float*)d_in[2];
    const float* b    = (const float*)d_in[3];
    const float* a    = (const float*)d_in[4];
    float* out = (float*)d_out;

    int nN = in_sizes[0] / IN_DIM;   // 50000
    int nE = in_sizes[1] / 2;        // 1600000

    int nbT = (nN + 255) / 256;
    int nbH = 1024;
    k_fused<<<nbT + nbH, 256>>>(x, W, b, a, eidx, nN, nE, nbT);

    int nbS = (nN + SCAN_BLK - 1) / SCAN_BLK;
    k_scan<<<nbS, SCAN_BLK>>>(nN);

    k_place<<<(nE + 255) / 256, 256>>>(eidx, nE, nN);
    k_aggregate<<<(nN + 15) / 16, 256>>>(out, nN);
}

// round 7
// speedup vs baseline: 1.0730x; 1.0730x over previous
#include <cuda_runtime.h>
#include <cuda_fp16.h>
#include <cstdint>

#define IN_DIM 128
#define OUT_DIM 64
#define MAXN 50000
#define MAXE 1600000
#define SLOPE 0.1f
#define EPS 1e-12f
#define SCAN_BLK 1024
#define MAX_SCAN_BLOCKS 64

// Scratch (static device globals — allocation is forbidden). Zero-init at load.
__device__ __align__(256) __half g_newh[MAXN * OUT_DIM]; // transformed features, fp16
__device__ float  g_ssrc[MAXN];          // new[n] . a_src
__device__ float  g_sdst[MAXN];          // new[n] . a_dst
__device__ int    g_cnt[MAXN];           // out-degree histogram (zeroed by k_aggregate)
__device__ int    g_base[MAXN];          // CSR offsets (mutated by k_place into end[])
__device__ __align__(16) float2 g_edge[MAXE];  // src-sorted {ev, dst_bits}
__device__ int    g_bsum[MAX_SCAN_BLOCKS];   // scan block aggregates
__device__ int    g_flag[MAX_SCAN_BLOCKS];   // scan publish flags (zeroed by k_fused)

// ---------------------------------------------------------------------------
// Kernel 1 (fused): blocks [0, nbT): transform new = x@W^T+b -> fp16, scores
//   (scalar FFMA, W broadcast from smem — the proven R4 form).
//   Blocks [nbT, ...): histogram of src. Block 0 zeroes scan flags.
// ---------------------------------------------------------------------------
__global__ __launch_bounds__(256) void k_fused(
    const float* __restrict__ x, const float* __restrict__ W,
    const float* __restrict__ b, const float* __restrict__ a,
    const int* __restrict__ eidx, int nN, int nE, int nbT)
{
    if ((int)blockIdx.x >= nbT) {
        // ---- histogram part ----
        int tidg   = (blockIdx.x - nbT) * blockDim.x + threadIdx.x;
        int stride = (gridDim.x - nbT) * blockDim.x;
        for (int e = tidg; e < nE; e += stride) {
            int s = eidx[e];
            s = min(max(s, 0), nN - 1);
            atomicAdd(&g_cnt[s], 1);
        }
        return;
    }

    // ---- transform part ----
    if (blockIdx.x == 0 && threadIdx.x < MAX_SCAN_BLOCKS) g_flag[threadIdx.x] = 0;

    __shared__ __align__(16) float sW[OUT_DIM * IN_DIM];
    __shared__ float sb[OUT_DIM], sas[OUT_DIM], sad[OUT_DIM];
    for (int i = threadIdx.x; i < OUT_DIM * IN_DIM; i += blockDim.x) sW[i] = W[i];
    if (threadIdx.x < OUT_DIM) {
        sb[threadIdx.x]  = b[threadIdx.x];
        sas[threadIdx.x] = a[threadIdx.x];
        sad[threadIdx.x] = a[OUT_DIM + threadIdx.x];
    }
    __syncthreads();

    int n = blockIdx.x * blockDim.x + threadIdx.x;
    if (n >= nN) return;

    const float4* __restrict__ x4 = (const float4*)(x + (size_t)n * IN_DIM);
    const float4* __restrict__ W4 = (const float4*)sW;

    float acc[OUT_DIM];
#pragma unroll
    for (int d = 0; d < OUT_DIM; d++) acc[d] = 0.f;

    for (int kk = 0; kk < IN_DIM / 4; kk++) {
        float4 xv = x4[kk];
#pragma unroll
        for (int d = 0; d < OUT_DIM; d++) {
            float4 wv = W4[d * (IN_DIM / 4) + kk];   // warp-broadcast from smem
            acc[d] += xv.x * wv.x + xv.y * wv.y + xv.z * wv.z + xv.w * wv.w;
        }
    }

    float ss = 0.f, sd = 0.f;
    uint2* newh = (uint2*)(g_newh + ((size_t)n << 6));
#pragma unroll
    for (int j = 0; j < OUT_DIM / 4; j++) {
        float v0 = acc[4*j+0] + sb[4*j+0];
        float v1 = acc[4*j+1] + sb[4*j+1];
        float v2 = acc[4*j+2] + sb[4*j+2];
        float v3 = acc[4*j+3] + sb[4*j+3];
        __half2 h0 = __float22half2_rn(make_float2(v0, v1));
        __half2 h1 = __float22half2_rn(make_float2(v2, v3));
        uint2 hv;
        hv.x = *(unsigned int*)&h0;
        hv.y = *(unsigned int*)&h1;
        newh[j] = hv;
        ss += v0*sas[4*j+0] + v1*sas[4*j+1] + v2*sas[4*j+2] + v3*sas[4*j+3];
        sd += v0*sad[4*j+0] + v1*sad[4*j+1] + v2*sad[4*j+2] + v3*sad[4*j+3];
    }
    g_ssrc[n] = ss;
    g_sdst[n] = sd;
}

// ---------------------------------------------------------------------------
// Kernel 2: exclusive scan of g_cnt -> g_base, decoupled lookback.
// 49 blocks, all concurrently resident so the spin cannot deadlock.
// ---------------------------------------------------------------------------
__global__ __launch_bounds__(SCAN_BLK) void k_scan(int nN)
{
    __shared__ int swarp[32];
    __shared__ int s_total;
    __shared__ int s_boff;
    int tid  = threadIdx.x;
    int lane = tid & 31;
    int wid  = tid >> 5;
    int bid  = blockIdx.x;
    int i    = bid * SCAN_BLK + tid;

    int v = (i < nN) ? g_cnt[i] : 0;

    int inc = v;
#pragma unroll
    for (int off = 1; off < 32; off <<= 1) {
        int t = __shfl_up_sync(0xFFFFFFFF, inc, off);
        if (lane >= off) inc += t;
    }
    if (lane == 31) swarp[wid] = inc;
    __syncthreads();
    if (wid == 0) {
        int wv = swarp[lane];
        int winc = wv;
#pragma unroll
        for (int off = 1; off < 32; off <<= 1) {
            int t = __shfl_up_sync(0xFFFFFFFF, winc, off);
            if (lane >= off) winc += t;
        }
        swarp[lane] = winc - wv;
    }
    __syncthreads();
    int incl = swarp[wid] + inc;
    if (tid == SCAN_BLK - 1) s_total = incl;
    __syncthreads();

    if (tid == 0) {
        g_bsum[bid] = s_total;
        __threadfence();
        *(volatile int*)&g_flag[bid] = 1;
    }

    if (wid == 0) {
        int off = 0;
        for (int base = 0; base < bid; base += 32) {
            int j = base + lane;
            int vj = 0;
            if (j < bid) {
                while (*(volatile int*)&g_flag[j] == 0) {}
                __threadfence();
                vj = *(volatile int*)&g_bsum[j];
            }
#pragma unroll
            for (int o = 16; o > 0; o >>= 1)
                vj += __shfl_down_sync(0xFFFFFFFF, vj, o);
            off += __shfl_sync(0xFFFFFFFF, vj, 0);
        }
        if (lane == 0) s_boff = off;
    }
    __syncthreads();

    if (i < nN) g_base[i] = s_boff + incl - v;
}

// ---------------------------------------------------------------------------
// Kernel 3: per-edge score -> ev once; place {ev,dst} into CSR slot.
// ---------------------------------------------------------------------------
__global__ __launch_bounds__(256) void k_place(
    const int* __restrict__ eidx, int nE, int nN)
{
    int e = blockIdx.x * blockDim.x + threadIdx.x;
    if (e >= nE) return;
    int s = eidx[e];
    int d = eidx[(size_t)nE + e];
    s = min(max(s, 0), nN - 1);
    d = min(max(d, 0), nN - 1);
    float sc = g_ssrc[s] + g_sdst[d];
    sc = sc > 0.f ? sc : SLOPE * sc;
    float ev = __expf(sc);
    int pos = atomicAdd(&g_base[s], 1);
    g_edge[pos] = make_float2(ev, __int_as_float(d));
}

// ---------------------------------------------------------------------------
// Kernel 4: gather-aggregate + normalize. 8 lanes/node, lane c owns 16B
// (8 halves) of the row: half the warp-instructions per edge vs 16-lane
// mapping at identical L2 sector traffic. Unrolled x4 for MLP.
// ---------------------------------------------------------------------------
__global__ __launch_bounds__(256) void k_aggregate(
    float* __restrict__ out, int nN)
{
    int n = blockIdx.x * 32 + (threadIdx.x >> 3);
    int c = threadIdx.x & 7;
    if (n >= nN) return;

    int beg = (n == 0) ? 0 : g_base[n - 1];
    int end = g_base[n];

    float acc[8];
#pragma unroll
    for (int j = 0; j < 8; j++) acc[j] = 0.f;
    float rs = 0.f;

    int i = beg;
    for (; i + 4 <= end; i += 4) {
        float2 p0 = g_edge[i];
        float2 p1 = g_edge[i + 1];
        float2 p2 = g_edge[i + 2];
        float2 p3 = g_edge[i + 3];
        uint4 h0 = *(const uint4*)(g_newh + ((size_t)__float_as_int(p0.y) << 6) + c * 8);
        uint4 h1 = *(const uint4*)(g_newh + ((size_t)__float_as_int(p1.y) << 6) + c * 8);
        uint4 h2 = *(const uint4*)(g_newh + ((size_t)__float_as_int(p2.y) << 6) + c * 8);
        uint4 h3 = *(const uint4*)(g_newh + ((size_t)__float_as_int(p3.y) << 6) + c * 8);
#pragma unroll
        for (int q = 0; q < 4; q++) {
            float ev = (q == 0) ? p0.x : (q == 1) ? p1.x : (q == 2) ? p2.x : p3.x;
            uint4 hv = (q == 0) ? h0 : (q == 1) ? h1 : (q == 2) ? h2 : h3;
            float2 f0 = __half22float2(*(__half2*)&hv.x);
            float2 f1 = __half22float2(*(__half2*)&hv.y);
            float2 f2 = __half22float2(*(__half2*)&hv.z);
            float2 f3 = __half22float2(*(__half2*)&hv.w);
            acc[0] += ev * f0.x;  acc[1] += ev * f0.y;
            acc[2] += ev * f1.x;  acc[3] += ev * f1.y;
            acc[4] += ev * f2.x;  acc[5] += ev * f2.y;
            acc[6] += ev * f3.x;  acc[7] += ev * f3.y;
            rs += ev;
        }
    }
    for (; i < end; i++) {
        float2 p = g_edge[i];
        uint4 hv = *(const uint4*)(g_newh + ((size_t)__float_as_int(p.y) << 6) + c * 8);
        float ev = p.x;
        float2 f0 = __half22float2(*(__half2*)&hv.x);
        float2 f1 = __half22float2(*(__half2*)&hv.y);
        float2 f2 = __half22float2(*(__half2*)&hv.z);
        float2 f3 = __half22float2(*(__half2*)&hv.w);
        acc[0] += ev * f0.x;  acc[1] += ev * f0.y;
        acc[2] += ev * f1.x;  acc[3] += ev * f1.y;
        acc[4] += ev * f2.x;  acc[5] += ev * f2.y;
        acc[6] += ev * f3.x;  acc[7] += ev * f3.y;
        rs += ev;
    }

    float inv = 1.f / (rs + EPS);
    float* op = out + ((size_t)n << 6) + c * 8;
    *(float4*)op       = make_float4(acc[0]*inv, acc[1]*inv, acc[2]*inv, acc[3]*inv);
    *(float4*)(op + 4) = make_float4(acc[4]*inv, acc[5]*inv, acc[6]*inv, acc[7]*inv);

    if (c == 0) g_cnt[n] = 0;   // clean for next launch (graph replay)
}

// ---------------------------------------------------------------------------
extern "C" void kernel_launch(void* const* d_in, const int* in_sizes, int n_in,
                              void* d_out, int out_size)
{
    const float* x    = (const float*)d_in[0];
    const int*   eidx = (const int*)d_in[1];    // int32 (JAX x64 disabled)
    const float* W    = (const float*)d_in[2];
    const float* b    = (const float*)d_in[3];
    const float* a    = (const float*)d_in[4];
    float* out = (float*)d_out;

    int nN = in_sizes[0] / IN_DIM;   // 50000
    int nE = in_sizes[1] / 2;        // 1600000

    int nbT = (nN + 255) / 256;
    int nbH = 1024;
    k_fused<<<nbT + nbH, 256>>>(x, W, b, a, eidx, nN, nE, nbT);

    int nbS = (nN + SCAN_BLK - 1) / SCAN_BLK;
    k_scan<<<nbS, SCAN_BLK>>>(nN);

    k_place<<<(nE + 255) / 256, 256>>>(eidx, nE, nN);
    k_aggregate<<<(nN + 31) / 32, 256>>>(out, nN);
}